// round 2
// baseline (speedup 1.0000x reference)
#include <cuda_runtime.h>
#include <cstdint>

// Problem constants
#define BATCH 32
#define CIN   128
#define COUT  256
#define HH    56
#define WW    56
#define HWPix (HH*WW)          // 3136
#define KTAPS 9
#define KTOT  (CIN*KTAPS)      // 1152

// Scratch (allocation-free rule: __device__ globals)
__device__ int8_t g_x8[(size_t)BATCH * HWPix * CIN];   // NHWC int8, 12.85 MB
__device__ int8_t g_w8[(size_t)COUT * KTOT];           // [n][tap][cin], 288 KB

// ---------------------------------------------------------------------------
// Kernel 1: x fp32 NCHW -> int8 NHWC. One thread per pixel (b,hw).
// ---------------------------------------------------------------------------
__global__ void convert_x_kernel(const float* __restrict__ x) {
    int tid = blockIdx.x * blockDim.x + threadIdx.x;   // 0 .. 100351
    int b  = tid / HWPix;
    int hw = tid - b * HWPix;
    const float* xb = x + (size_t)b * CIN * HWPix + hw;
    int8_t* dst = g_x8 + (size_t)tid * CIN;
#pragma unroll
    for (int c0 = 0; c0 < CIN; c0 += 16) {
        uint32_t pk[4];
#pragma unroll
        for (int j = 0; j < 4; j++) {
            uint32_t v = 0;
#pragma unroll
            for (int k = 0; k < 4; k++) {
                int c = c0 + j * 4 + k;
                int val = __float2int_rn(xb[(size_t)c * HWPix]);
                v |= (uint32_t)(val & 0xFF) << (8 * k);
            }
            pk[j] = v;
        }
        *(int4*)(dst + c0) = make_int4((int)pk[0], (int)pk[1], (int)pk[2], (int)pk[3]);
    }
}

// ---------------------------------------------------------------------------
// Kernel 2: weight fp32 OIHW -> int8 [n][tap][cin]
// ---------------------------------------------------------------------------
__global__ void convert_w_kernel(const float* __restrict__ w) {
    int tid = blockIdx.x * blockDim.x + threadIdx.x;   // 0 .. 294911
    int n   = tid / KTOT;
    int r   = tid - n * KTOT;
    int tap = r / CIN;
    int c   = r - tap * CIN;
    int val = __float2int_rn(w[((size_t)(n * CIN + c)) * KTAPS + tap]);
    g_w8[tid] = (int8_t)val;
}

// ---------------------------------------------------------------------------
// Kernel 3: implicit-GEMM conv via mma.sync.m16n8k32.s8
// CTA: 128 threads (4 warps as 2x2), tile M=64 pixels x N=128 outchannels.
// Output: float32 carriers of the int8 result (per __output__ dtype).
// ---------------------------------------------------------------------------
#define PA 144   // A smem pitch (bytes)
#define PB 144   // B smem pitch (bytes)

__device__ __forceinline__ void mma_s8(int* c, const int* a, int b0, int b1) {
    asm volatile(
        "mma.sync.aligned.m16n8k32.row.col.s32.s8.s8.s32 "
        "{%0,%1,%2,%3}, {%4,%5,%6,%7}, {%8,%9}, {%0,%1,%2,%3};\n"
        : "+r"(c[0]), "+r"(c[1]), "+r"(c[2]), "+r"(c[3])
        : "r"(a[0]), "r"(a[1]), "r"(a[2]), "r"(a[3]), "r"(b0), "r"(b1));
}

__global__ void __launch_bounds__(128, 4)
conv_mma_kernel(const float* __restrict__ tbias,
                const int*   __restrict__ nshift,
                const int*   __restrict__ amin,
                const int*   __restrict__ amax,
                float*       __restrict__ out) {
    __shared__ __align__(16) int8_t smA[64 * PA];
    __shared__ __align__(16) int8_t smB[128 * PB];

    const int tid  = threadIdx.x;
    const int lane = tid & 31;
    const int warp = tid >> 5;
    const int warpM = warp >> 1;         // 0..1, covers 32 M-rows
    const int warpN = warp & 1;          // 0..1, covers 64 N-cols
    const int g   = lane >> 2;
    const int tig = lane & 3;

    const int m0  = blockIdx.x * 64;     // pixel base; 3136 % 64 == 0 -> never spans b
    const int b   = m0 / HWPix;
    const int hw0 = m0 - b * HWPix;
    const int n0  = blockIdx.y * 128;

    int acc[2][8][4];
#pragma unroll
    for (int i = 0; i < 2; i++)
#pragma unroll
        for (int j = 0; j < 8; j++)
#pragma unroll
            for (int k = 0; k < 4; k++) acc[i][j][k] = 0;

    for (int tap = 0; tap < KTAPS; tap++) {
        const int dh = tap / 3 - 1;
        const int dw = tap % 3 - 1;
        __syncthreads();
        // ---- load A slab: 64 rows x 128B (im2col gather, zero padding) ----
        {
            int r    = tid >> 1;
            int half = tid & 1;
            int hw = hw0 + r;
            int h  = hw / WW;
            int wq = hw - h * WW;
            int hs = h + dh, ws = wq + dw;
            bool valid = ((unsigned)hs < HH) && ((unsigned)ws < WW);
            int sidx = valid ? (b * HWPix + hs * WW + ws) : 0;
            const int8_t* src = g_x8 + ((size_t)sidx << 7) + half * 64;
            int8_t* dst = smA + r * PA + half * 64;
#pragma unroll
            for (int i = 0; i < 4; i++) {
                int4 v = valid ? *(const int4*)(src + i * 16) : make_int4(0, 0, 0, 0);
                *(int4*)(dst + i * 16) = v;
            }
        }
        // ---- load B slab: 128 outchannels x 128B ----
        {
            const int8_t* src = g_w8 + (size_t)(n0 + tid) * KTOT + tap * CIN;
            int8_t* dst = smB + tid * PB;
#pragma unroll
            for (int i = 0; i < 8; i++)
                *(int4*)(dst + i * 16) = *(const int4*)(src + i * 16);
        }
        __syncthreads();
        // ---- 4 x k32 chunks of mma ----
#pragma unroll
        for (int k0 = 0; k0 < 128; k0 += 32) {
            int a[2][4];
#pragma unroll
            for (int mi = 0; mi < 2; mi++) {
                const int8_t* base = smA + (warpM * 32 + mi * 16 + g) * PA + k0 + 4 * tig;
                a[mi][0] = *(const int*)(base);
                a[mi][1] = *(const int*)(base + 8 * PA);
                a[mi][2] = *(const int*)(base + 16);
                a[mi][3] = *(const int*)(base + 8 * PA + 16);
            }
#pragma unroll
            for (int tn = 0; tn < 8; tn++) {
                const int8_t* bb = smB + (warpN * 64 + tn * 8 + g) * PB + k0 + 4 * tig;
                int b0 = *(const int*)(bb);
                int b1 = *(const int*)(bb + 16);
                mma_s8(acc[0][tn], a[0], b0, b1);
                mma_s8(acc[1][tn], a[1], b0, b1);
            }
        }
    }

    // ---- epilogue: bias + arithmetic shift + clamp -> float32 out ----
    // Direct stores: lanes sharing tig, varying g write 8 consecutive floats
    // (full 32B sectors); each warp STG covers 4 fully-utilized sectors.
    const float* outBase = out;  (void)outBase;
#pragma unroll
    for (int tn = 0; tn < 8; tn++) {
#pragma unroll
        for (int cb = 0; cb < 2; cb++) {
            int nl = warpN * 64 + tn * 8 + 2 * tig + cb;
            int ng = n0 + nl;
            int tb = __float2int_rn(__ldg(&tbias[ng]));
            int sh = -__ldg(&nshift[ng]);     // n is negative; shift amount = -n
            int mn = __ldg(&amin[ng]);
            int mx = __ldg(&amax[ng]);
            float* rowp = out + ((size_t)b * COUT + ng) * HWPix + hw0;
#pragma unroll
            for (int mi = 0; mi < 2; mi++) {
#pragma unroll
                for (int rh = 0; rh < 2; rh++) {
                    int v = acc[mi][tn][rh * 2 + cb];
                    v = (v + tb) >> sh;              // arithmetic shift (matches jnp)
                    v = max(mn, min(mx, v));
                    int ml = warpM * 32 + mi * 16 + rh * 8 + g;
                    rowp[ml] = (float)v;
                }
            }
        }
    }
}

// ---------------------------------------------------------------------------
// Launch
// ---------------------------------------------------------------------------
extern "C" void kernel_launch(void* const* d_in, const int* in_sizes, int n_in,
                              void* d_out, int out_size) {
    const float* x      = (const float*)d_in[0];
    const float* weight = (const float*)d_in[1];
    const float* tbias  = (const float*)d_in[2];
    const int*   nsh    = (const int*)d_in[3];
    const int*   amin   = (const int*)d_in[4];
    const int*   amax   = (const int*)d_in[5];
    float* out = (float*)d_out;

    convert_x_kernel<<<(BATCH * HWPix) / 256, 256>>>(x);                 // 392 blocks
    convert_w_kernel<<<(COUT * KTOT) / 256, 256>>>(weight);              // 1152 blocks
    dim3 grid(BATCH * (HWPix / 64), COUT / 128);                         // 1568 x 2
    conv_mma_kernel<<<grid, 128>>>(tbias, nsh, amin, amax, out);
}

// round 3
// speedup vs baseline: 1.2077x; 1.2077x over previous
#include <cuda_runtime.h>
#include <cstdint>

// Problem constants
#define BATCH 32
#define CIN   128
#define COUT  256
#define HH    56
#define WW    56
#define HWPix (HH*WW)          // 3136
#define KTAPS 9
#define KTOT  (CIN*KTAPS)      // 1152

#define PA 144                 // A smem pitch (bytes), 16B aligned, LDSM conflict-free
#define PB 144                 // B smem pitch
#define ABUF (64*PA)           // 9216
#define BBUF (256*PB)          // 36864
#define BUFSZ (ABUF + BBUF)    // 46080
#define SMEM_TOTAL (2*BUFSZ)   // 92160

// Scratch (allocation-free rule: __device__ globals)
__device__ __align__(128) int8_t g_x8[(size_t)BATCH * HWPix * CIN];   // NHWC int8
__device__ __align__(128) int8_t g_w8[(size_t)COUT * KTOT];           // [n][tap][cin]

// ---------------------------------------------------------------------------
// Kernel 1: x fp32 NCHW -> int8 NHWC. Thread per (pixel, 32-channel group).
// ---------------------------------------------------------------------------
__global__ void convert_x_kernel(const float* __restrict__ x) {
    int idx = blockIdx.x * blockDim.x + threadIdx.x;   // 0 .. 401407
    int pix = idx >> 2;
    int c0  = (idx & 3) << 5;
    int b   = pix / HWPix;
    int hw  = pix - b * HWPix;
    const float* xb = x + (size_t)b * CIN * HWPix + (size_t)c0 * HWPix + hw;
    int8_t* dst = g_x8 + (size_t)pix * CIN + c0;
#pragma unroll
    for (int j = 0; j < 2; j++) {
        uint32_t pk[4];
#pragma unroll
        for (int jj = 0; jj < 4; jj++) {
            uint32_t v = 0;
#pragma unroll
            for (int k = 0; k < 4; k++) {
                int c = j * 16 + jj * 4 + k;
                int val = __float2int_rn(xb[(size_t)c * HWPix]);
                v |= (uint32_t)(val & 0xFF) << (8 * k);
            }
            pk[jj] = v;
        }
        *(int4*)(dst + j * 16) = make_int4((int)pk[0], (int)pk[1], (int)pk[2], (int)pk[3]);
    }
}

// ---------------------------------------------------------------------------
// Kernel 2: weight fp32 OIHW -> int8 [n][tap][cin]
// ---------------------------------------------------------------------------
__global__ void convert_w_kernel(const float* __restrict__ w) {
    int tid = blockIdx.x * blockDim.x + threadIdx.x;   // 0 .. 294911
    int n   = tid / KTOT;
    int r   = tid - n * KTOT;
    int tap = r / CIN;
    int c   = r - tap * CIN;
    int val = __float2int_rn(w[((size_t)(n * CIN + c)) * KTAPS + tap]);
    g_w8[tid] = (int8_t)val;
}

// ---------------------------------------------------------------------------
// Kernel 3: implicit-GEMM conv. CTA tile M=64 x N=256, 256 threads (2Mx4N warps).
// cp.async double-buffered over the 9 taps; ldmatrix fragment loads.
// ---------------------------------------------------------------------------
__device__ __forceinline__ void mma_s8(int* c, const int* a, int b0, int b1) {
    asm volatile(
        "mma.sync.aligned.m16n8k32.row.col.s32.s8.s8.s32 "
        "{%0,%1,%2,%3}, {%4,%5,%6,%7}, {%8,%9}, {%0,%1,%2,%3};\n"
        : "+r"(c[0]), "+r"(c[1]), "+r"(c[2]), "+r"(c[3])
        : "r"(a[0]), "r"(a[1]), "r"(a[2]), "r"(a[3]), "r"(b0), "r"(b1));
}

#define CPA16(dst, src, sz) \
    asm volatile("cp.async.cg.shared.global [%0], [%1], 16, %2;\n" \
                 :: "r"(dst), "l"(src), "r"(sz))
#define CPA_COMMIT() asm volatile("cp.async.commit_group;\n")

__global__ void __launch_bounds__(256, 2)
conv_mma_kernel(const float* __restrict__ tbias,
                const int*   __restrict__ nshift,
                const int*   __restrict__ amin,
                const int*   __restrict__ amax,
                float*       __restrict__ out) {
    extern __shared__ __align__(16) int8_t smem[];
    const uint32_t smem_u32 = (uint32_t)__cvta_generic_to_shared(smem);

    const int tid  = threadIdx.x;
    const int lane = tid & 31;
    const int warp = tid >> 5;
    const int warpM = warp >> 2;         // 0..1 -> 32 M-rows
    const int warpN = warp & 3;          // 0..3 -> 64 N-cols
    const int g   = lane >> 2;
    const int tig = lane & 3;

    const int m0  = blockIdx.x * 64;     // 3136 % 64 == 0 -> tile never spans batch
    const int b   = m0 / HWPix;
    const int hw0 = m0 - b * HWPix;

    // per-thread A-loader invariants: row = tid>>2 (0..63), quarter = tid&3
    const int ar = tid >> 2, aq = tid & 3;
    const int ahw = hw0 + ar;
    const int ah  = ahw / WW;
    const int aw  = ahw - ah * WW;
    // B-loader: one 128B weight row per thread
    const int8_t* wsrc_base = g_w8 + (size_t)tid * KTOT;

    int acc[2][8][4];
#pragma unroll
    for (int i = 0; i < 2; i++)
#pragma unroll
        for (int j = 0; j < 8; j++)
#pragma unroll
            for (int k = 0; k < 4; k++) acc[i][j][k] = 0;

    // ---- tap loader (cp.async into buffer buf) ----
    auto load_tap = [&](int tap, int buf) {
        const int dh = tap / 3 - 1;
        const int dw = tap % 3 - 1;
        // A slab: 64 rows x 128B, zero-fill padding rows via src-size=0
        {
            int hs = ah + dh, ws = aw + dw;
            bool valid = ((unsigned)hs < HH) && ((unsigned)ws < WW);
            int sidx = valid ? (b * HWPix + hs * WW + ws) : 0;
            const int8_t* src = g_x8 + ((size_t)sidx << 7) + aq * 32;
            uint32_t dst = smem_u32 + buf * BUFSZ + ar * PA + aq * 32;
            int sz = valid ? 16 : 0;
            CPA16(dst,      src,      sz);
            CPA16(dst + 16, src + 16, sz);
        }
        // B slab: 256 rows x 128B
        {
            const int8_t* src = wsrc_base + tap * CIN;
            uint32_t dst = smem_u32 + buf * BUFSZ + ABUF + tid * PB;
#pragma unroll
            for (int i = 0; i < 8; i++)
                CPA16(dst + i * 16, src + i * 16, 16);
        }
        CPA_COMMIT();
    };

    // ---- compute one tap from buffer buf ----
    auto compute = [&](int buf) {
        const uint32_t baseA = smem_u32 + buf * BUFSZ;
        const uint32_t baseB = baseA + ABUF;
#pragma unroll
        for (int k0 = 0; k0 < 128; k0 += 32) {
            int a[2][4];
#pragma unroll
            for (int mi = 0; mi < 2; mi++) {
                int row = warpM * 32 + mi * 16 + (lane & 15);
                int col = k0 + ((lane >> 4) << 4);
                uint32_t addr = baseA + row * PA + col;
                asm volatile(
                    "ldmatrix.sync.aligned.m8n8.x4.shared.b16 {%0,%1,%2,%3}, [%4];\n"
                    : "=r"(a[mi][0]), "=r"(a[mi][1]), "=r"(a[mi][2]), "=r"(a[mi][3])
                    : "r"(addr));
            }
#pragma unroll
            for (int tp = 0; tp < 4; tp++) {
                int tile = lane >> 3;
                int tn   = tp * 2 + (tile >> 1);
                int row  = warpN * 64 + tn * 8 + (lane & 7);
                int col  = k0 + ((tile & 1) << 4);
                uint32_t addr = baseB + row * PB + col;
                int b0, b1, b2, b3;
                asm volatile(
                    "ldmatrix.sync.aligned.m8n8.x4.shared.b16 {%0,%1,%2,%3}, [%4];\n"
                    : "=r"(b0), "=r"(b1), "=r"(b2), "=r"(b3)
                    : "r"(addr));
                mma_s8(acc[0][tp * 2],     a[0], b0, b1);
                mma_s8(acc[1][tp * 2],     a[1], b0, b1);
                mma_s8(acc[0][tp * 2 + 1], a[0], b2, b3);
                mma_s8(acc[1][tp * 2 + 1], a[1], b2, b3);
            }
        }
    };

    // ---- software pipeline over taps ----
    load_tap(0, 0);
#pragma unroll 1
    for (int tap = 0; tap < KTAPS; tap++) {
        if (tap < KTAPS - 1) {
            load_tap(tap + 1, (tap + 1) & 1);
            asm volatile("cp.async.wait_group 1;\n");
        } else {
            asm volatile("cp.async.wait_group 0;\n");
        }
        __syncthreads();
        compute(tap & 1);
        __syncthreads();   // buffer consumed; next iteration may overwrite it
    }

    // ---- epilogue: bias + arithmetic shift + clamp -> float32 out ----
#pragma unroll
    for (int tn = 0; tn < 8; tn++) {
#pragma unroll
        for (int cb = 0; cb < 2; cb++) {
            int ng = warpN * 64 + tn * 8 + 2 * tig + cb;
            int tb = __float2int_rn(__ldg(&tbias[ng]));
            int sh = -__ldg(&nshift[ng]);
            int mn = __ldg(&amin[ng]);
            int mx = __ldg(&amax[ng]);
            float* rowp = out + ((size_t)b * COUT + ng) * HWPix + hw0;
#pragma unroll
            for (int mi = 0; mi < 2; mi++) {
#pragma unroll
                for (int rh = 0; rh < 2; rh++) {
                    int v = acc[mi][tn][rh * 2 + cb];
                    v = (v + tb) >> sh;
                    v = max(mn, min(mx, v));
                    int ml = warpM * 32 + mi * 16 + rh * 8 + g;
                    rowp[ml] = (float)v;
                }
            }
        }
    }
}

// ---------------------------------------------------------------------------
// Launch
// ---------------------------------------------------------------------------
extern "C" void kernel_launch(void* const* d_in, const int* in_sizes, int n_in,
                              void* d_out, int out_size) {
    const float* x      = (const float*)d_in[0];
    const float* weight = (const float*)d_in[1];
    const float* tbias  = (const float*)d_in[2];
    const int*   nsh    = (const int*)d_in[3];
    const int*   amin   = (const int*)d_in[4];
    const int*   amax   = (const int*)d_in[5];
    float* out = (float*)d_out;

    cudaFuncSetAttribute(conv_mma_kernel,
                         cudaFuncAttributeMaxDynamicSharedMemorySize, SMEM_TOTAL);

    convert_x_kernel<<<(BATCH * HWPix * 4) / 256, 256>>>(x);             // 1568 blocks
    convert_w_kernel<<<(COUT * KTOT) / 256, 256>>>(weight);              // 1152 blocks
    conv_mma_kernel<<<BATCH * (HWPix / 64), 256, SMEM_TOTAL>>>(tbias, nsh, amin, amax, out);
}